// round 4
// baseline (speedup 1.0000x reference)
#include <cuda_runtime.h>
#include <cuda_bf16.h>
#include <cstdint>

#define BQ 8192
#define HDIM 512
#define HK 8192
#define NT2 32               // gemm2 n-tiles = 8192/256
#define NC 24                // k-chunks: 3 segments x (512/64)
#define STAGE_BYTES 49152    // A 16KB + B 32KB
#define DYNSMEM 196608       // 4 stages
#define CSTRIDE 264          // fp32 C stage row stride

// ---------------- device scratch (no cudaMalloc allowed) -------------------
__device__ __align__(16) __nv_bfloat16 g_a1h[BQ*HDIM];
__device__ __align__(16) __nv_bfloat16 g_a1l[BQ*HDIM];
__device__ __align__(16) __nv_bfloat16 g_hh [BQ*HDIM];
__device__ __align__(16) __nv_bfloat16 g_hl [BQ*HDIM];
__device__ __align__(16) __nv_bfloat16 g_w1h[HDIM*HDIM];
__device__ __align__(16) __nv_bfloat16 g_w1l[HDIM*HDIM];
__device__ __align__(16) __nv_bfloat16 g_w2h[(size_t)HK*HDIM];
__device__ __align__(16) __nv_bfloat16 g_w2l[(size_t)HK*HDIM];
__device__ float g_ldp[(size_t)BQ*NT2];

// ---------------- helpers ---------------------------------------------------
__device__ __forceinline__ uint32_t smem_u32(const void* p){
    uint32_t a;
    asm("{ .reg .u64 t; cvta.to.shared.u64 t, %1; cvt.u32.u64 %0, t; }" : "=r"(a) : "l"(p));
    return a;
}
__device__ __forceinline__ void cp16(uint32_t dst, const void* src){
    asm volatile("cp.async.cg.shared.global [%0], [%1], 16;" :: "r"(dst), "l"(src));
}
__device__ __forceinline__ void cp_commit(){
    asm volatile("cp.async.commit_group;" ::: "memory");
}
template<int N> __device__ __forceinline__ void cp_wait(){
    asm volatile("cp.async.wait_group %0;" :: "n"(N) : "memory");
}
__device__ __forceinline__ void ldsm4(uint32_t* r, uint32_t addr){
    asm volatile("ldmatrix.sync.aligned.m8n8.x4.shared.b16 {%0,%1,%2,%3}, [%4];"
        : "=r"(r[0]), "=r"(r[1]), "=r"(r[2]), "=r"(r[3]) : "r"(addr));
}
__device__ __forceinline__ void mma16816(float* d, const uint32_t* a, const uint32_t* b){
    asm volatile("mma.sync.aligned.m16n8k16.row.col.f32.bf16.bf16.f32 "
        "{%0,%1,%2,%3},{%4,%5,%6,%7},{%8,%9},{%0,%1,%2,%3};"
        : "+f"(d[0]), "+f"(d[1]), "+f"(d[2]), "+f"(d[3])
        : "r"(a[0]), "r"(a[1]), "r"(a[2]), "r"(a[3]), "r"(b[0]), "r"(b[1]));
}
__device__ __forceinline__ float fast_tanh(float x){
    x = fminf(fmaxf(x, -15.f), 15.f);
    float e = __expf(2.f * x);
    return __fdividef(e - 1.f, e + 1.f);
}

// ---------------- mainloop --------------------------------------------------
// Tile 128 x 256, 8 warps (2m x 4n), warp tile 64x64.
// A: [rows, 512] bf16 hi/lo (k contiguous). B: Wt [Ntot, 512] bf16 hi/lo.
__device__ __forceinline__ void issue_chunk(
    int c, uint32_t sbase,
    const __nv_bfloat16* __restrict__ ah, const __nv_bfloat16* __restrict__ al,
    const __nv_bfloat16* __restrict__ bh, const __nv_bfloat16* __restrict__ bl,
    int row0, int n0, int tid)
{
    const int seg = c >> 3;
    const int kk  = (c & 7) << 6;
    const __nv_bfloat16* a = (seg == 1) ? al : ah;
    const __nv_bfloat16* b = (seg == 2) ? bl : bh;
#pragma unroll
    for (int j = 0; j < 4; ++j) {                // A: 128 rows x 128B
        int i = tid + 256 * j;
        int r = i >> 3, q = i & 7;
        uint32_t sw = (uint32_t)(r * 128) + ((uint32_t)(q ^ (r & 7)) << 4);
        cp16(sbase + sw, a + (size_t)(row0 + r) * HDIM + kk + q * 8);
    }
#pragma unroll
    for (int j = 0; j < 8; ++j) {                // B: 256 n-rows x 128B
        int i = tid + 256 * j;
        int r = i >> 3, q = i & 7;
        uint32_t sw = (uint32_t)(r * 128) + ((uint32_t)(q ^ (r & 7)) << 4);
        cp16(sbase + 16384u + sw, b + (size_t)(n0 + r) * HDIM + kk + q * 8);
    }
    cp_commit();
}

__device__ __forceinline__ void gemm_mainloop(
    const __nv_bfloat16* ah, const __nv_bfloat16* al,
    const __nv_bfloat16* bh, const __nv_bfloat16* bl,
    int row0, int n0, char* dsm, float* Csmem)
{
    const int tid  = threadIdx.x;
    const int wid  = tid >> 5;
    const int lane = tid & 31;
    const int wm   = wid & 1;          // m-half (64 rows)
    const int wn   = wid >> 1;         // n-quarter (64 cols)
    const uint32_t sb = smem_u32(dsm);

    float acc[4][8][4];
#pragma unroll
    for (int mi = 0; mi < 4; ++mi)
#pragma unroll
        for (int t = 0; t < 8; ++t)
#pragma unroll
            for (int q = 0; q < 4; ++q) acc[mi][t][q] = 0.f;

    const int arow = wm * 64 + (lane & 15);
    const int ahl  = lane >> 4;
    const int brow = wn * 64 + (lane & 7) + ((lane >> 4) << 3);
    const int bhl  = (lane >> 3) & 1;

    issue_chunk(0, sb,                   ah, al, bh, bl, row0, n0, tid);
    issue_chunk(1, sb + STAGE_BYTES,     ah, al, bh, bl, row0, n0, tid);
    issue_chunk(2, sb + 2 * STAGE_BYTES, ah, al, bh, bl, row0, n0, tid);

    for (int i = 0; i < NC; ++i) {
        if      (i < NC - 2) cp_wait<2>();
        else if (i == NC - 2) cp_wait<1>();
        else                  cp_wait<0>();
        __syncthreads();

        uint32_t ab = sb + (uint32_t)(i & 3) * STAGE_BYTES;
        uint32_t bb = ab + 16384u;
#pragma unroll
        for (int ks = 0; ks < 4; ++ks) {
            uint32_t af[4][4], bf[4][4];
#pragma unroll
            for (int mi = 0; mi < 4; ++mi) {
                int r = arow + mi * 16;
                uint32_t addr = ab + (uint32_t)(r * 128)
                              + ((uint32_t)((ks * 2 + ahl) ^ (r & 7)) << 4);
                ldsm4(af[mi], addr);
            }
#pragma unroll
            for (int bi = 0; bi < 4; ++bi) {
                int r = brow + bi * 16;
                uint32_t addr = bb + (uint32_t)(r * 128)
                              + ((uint32_t)((ks * 2 + bhl) ^ (r & 7)) << 4);
                ldsm4(bf[bi], addr);
            }
#pragma unroll
            for (int mi = 0; mi < 4; ++mi)
#pragma unroll
                for (int t = 0; t < 8; ++t)
                    mma16816(acc[mi][t], af[mi], &bf[t >> 1][(t & 1) * 2]);
        }
        int j = i + 3;
        if (j < NC)
            issue_chunk(j, sb + (uint32_t)(j & 3) * STAGE_BYTES,
                        ah, al, bh, bl, row0, n0, tid);
    }

    // stage C to smem (aliases stage slots 0..2; slot 3 held last chunk)
    const int gid = lane >> 2;
    const int c0  = wn * 64 + (lane & 3) * 2;
#pragma unroll
    for (int mi = 0; mi < 4; ++mi) {
        int r = wm * 64 + mi * 16 + gid;
#pragma unroll
        for (int t = 0; t < 8; ++t) {
            *(float2*)&Csmem[(size_t)r * CSTRIDE + c0 + t * 8] =
                make_float2(acc[mi][t][0], acc[mi][t][1]);
            *(float2*)&Csmem[(size_t)(r + 8) * CSTRIDE + c0 + t * 8] =
                make_float2(acc[mi][t][2], acc[mi][t][3]);
        }
    }
    __syncthreads();
}

// ---------------- GEMM1: h = tanh((v_p-0.5)@W1+b1) -> bf16 hi/lo ------------
__global__ __launch_bounds__(256, 1) void k_gemm1_tc(const float* __restrict__ b1)
{
    extern __shared__ char dsm[];
    float* Csmem = (float*)dsm;
    const int row0 = blockIdx.y * 128;
    const int n0   = blockIdx.x * 256;

    gemm_mainloop(g_a1h, g_a1l, g_w1h, g_w1l, row0, n0, dsm, Csmem);

    const int tid = threadIdx.x;
    const int r   = tid >> 1;
    const int ch  = (tid & 1) * 128;
    const int row = row0 + r;
#pragma unroll 4
    for (int c = 0; c < 128; c += 4) {
        float4 v = *(float4*)&Csmem[(size_t)r * CSTRIDE + ch + c];
        int cg = n0 + ch + c;
        float t0 = fast_tanh(v.x + b1[cg + 0]);
        float t1 = fast_tanh(v.y + b1[cg + 1]);
        float t2 = fast_tanh(v.z + b1[cg + 2]);
        float t3 = fast_tanh(v.w + b1[cg + 3]);
        __nv_bfloat16 h0 = __float2bfloat16(t0), h1 = __float2bfloat16(t1);
        __nv_bfloat16 h2 = __float2bfloat16(t2), h3 = __float2bfloat16(t3);
        __nv_bfloat162 ha; ha.x = h0; ha.y = h1;
        __nv_bfloat162 hb; hb.x = h2; hb.y = h3;
        __nv_bfloat162 la, lb;
        la.x = __float2bfloat16(t0 - __bfloat162float(h0));
        la.y = __float2bfloat16(t1 - __bfloat162float(h1));
        lb.x = __float2bfloat16(t2 - __bfloat162float(h2));
        lb.y = __float2bfloat16(t3 - __bfloat162float(h3));
        *(__nv_bfloat162*)&g_hh[(size_t)row * HDIM + cg]     = ha;
        *(__nv_bfloat162*)&g_hh[(size_t)row * HDIM + cg + 2] = hb;
        *(__nv_bfloat162*)&g_hl[(size_t)row * HDIM + cg]     = la;
        *(__nv_bfloat162*)&g_hl[(size_t)row * HDIM + cg + 2] = lb;
    }
}

// ---------------- GEMM2 fused: tanh->softmax(16)->spline->logp --------------
__global__ __launch_bounds__(256, 1) void k_gemm2_tc(
    const float* __restrict__ v_in, const float* __restrict__ b2,
    float* __restrict__ dout)
{
    extern __shared__ char dsm[];
    float* Csmem = (float*)dsm;
    float* red   = (float*)(dsm + 128 * CSTRIDE * 4);   // [128][16], within slots 0..2
    const int row0 = blockIdx.y * 128;
    const int n0   = blockIdx.x * 256;
    const int hbase = n0 >> 4;                           // 16 h per tile

    gemm_mainloop(g_hh, g_hl, g_w2h, g_w2l, row0, n0, dsm, Csmem);

    const int tid = threadIdx.x;
#pragma unroll 1
    for (int p = 0; p < 8; ++p) {
        int idx = p * 256 + tid;          // 2048 (row, group) pairs
        int r = idx >> 4, g = idx & 15;
        float e[16]; float sum = 0.f;
        const float* crow = &Csmem[(size_t)r * CSTRIDE + g * 16];
#pragma unroll
        for (int j4 = 0; j4 < 4; ++j4) {
            float4 cv = *(const float4*)&crow[j4 * 4];
            float t0 = fast_tanh(cv.x + b2[n0 + g * 16 + j4 * 4 + 0]);
            float t1 = fast_tanh(cv.y + b2[n0 + g * 16 + j4 * 4 + 1]);
            float t2 = fast_tanh(cv.z + b2[n0 + g * 16 + j4 * 4 + 2]);
            float t3 = fast_tanh(cv.w + b2[n0 + g * 16 + j4 * 4 + 3]);
            e[j4*4+0] = __expf(t0); e[j4*4+1] = __expf(t1);
            e[j4*4+2] = __expf(t2); e[j4*4+3] = __expf(t3);
            sum += e[j4*4+0] + e[j4*4+1] + e[j4*4+2] + e[j4*4+3];
        }
        int h = hbase + g;
        float v = v_in[(size_t)(row0 + r) * 1024 + 512 + h];
        int kk = (int)(v * 16.f); kk = kk < 0 ? 0 : (kk > 15 ? 15 : kk);
        float pref = 0.f, pk = 0.f;
#pragma unroll
        for (int j = 0; j < 16; ++j) {
            if (j < kk)  pref += e[j];
            if (j == kk) pk = e[j];
        }
        float inv   = __fdividef(1.f, sum);
        float p_k   = pk * inv;
        float ylo   = pref * inv;
        float alpha = v * 16.f - (float)kk;
        dout[(size_t)(row0 + r) * 1024 + 512 + h] = ylo + alpha * p_k;
        red[r * 16 + g] = __logf(p_k);
    }
    __syncthreads();
    if (tid < 128) {
        float s = 0.f;
#pragma unroll
        for (int g = 0; g < 16; ++g) s += red[tid * 16 + g];
        g_ldp[(size_t)(row0 + tid) * NT2 + blockIdx.x] = s;
    }
}

// ---------------- prep + finalize -------------------------------------------
__global__ __launch_bounds__(256) void k_prep_a1(const float* __restrict__ v_in,
                                                 float* __restrict__ out)
{
    int i = blockIdx.x * 256 + threadIdx.x;          // float4 over [BQ,128]
    if (i >= BQ * 128) return;
    int row = i >> 7, c4 = i & 127;
    float4 v = ((const float4*)v_in)[(size_t)row * 256 + c4];
    ((float4*)out)[(size_t)row * 256 + c4] = v;       // passive copy
    float a[4] = {v.x - 0.5f, v.y - 0.5f, v.z - 0.5f, v.w - 0.5f};
    __nv_bfloat162 h2[2], l2[2];
#pragma unroll
    for (int p = 0; p < 2; ++p) {
        __nv_bfloat16 h0 = __float2bfloat16(a[2*p]), h1 = __float2bfloat16(a[2*p+1]);
        h2[p].x = h0; h2[p].y = h1;
        l2[p].x = __float2bfloat16(a[2*p]   - __bfloat162float(h0));
        l2[p].y = __float2bfloat16(a[2*p+1] - __bfloat162float(h1));
    }
    __nv_bfloat162* ph = (__nv_bfloat162*)&g_a1h[(size_t)row * HDIM + c4 * 4];
    __nv_bfloat162* pl = (__nv_bfloat162*)&g_a1l[(size_t)row * HDIM + c4 * 4];
    ph[0] = h2[0]; ph[1] = h2[1];
    pl[0] = l2[0]; pl[1] = l2[1];
}

__device__ __forceinline__ void prep_wt_body(
    const float* __restrict__ W, __nv_bfloat16* th, __nv_bfloat16* tl, int N)
{
    __shared__ float t[32][33];
    int n0 = blockIdx.x * 32, k0 = blockIdx.y * 32;
    int tx = threadIdx.x, ty = threadIdx.y;
#pragma unroll
    for (int i = 0; i < 4; ++i)
        t[ty + 8 * i][tx] = W[(size_t)(k0 + ty + 8 * i) * N + n0 + tx];
    __syncthreads();
#pragma unroll
    for (int i = 0; i < 4; ++i) {
        float v = t[tx][ty + 8 * i];
        __nv_bfloat16 hi = __float2bfloat16(v);
        th[(size_t)(n0 + ty + 8 * i) * HDIM + k0 + tx] = hi;
        tl[(size_t)(n0 + ty + 8 * i) * HDIM + k0 + tx] =
            __float2bfloat16(v - __bfloat162float(hi));
    }
}
__global__ void k_prep_w1(const float* __restrict__ W){ prep_wt_body(W, g_w1h, g_w1l, HDIM); }
__global__ void k_prep_w2(const float* __restrict__ W){ prep_wt_body(W, g_w2h, g_w2l, HK);   }

__global__ __launch_bounds__(256) void k_finalize(const float* __restrict__ logd,
                                                  float* __restrict__ dout)
{
    int b = blockIdx.x * 256 + threadIdx.x;
    if (b < BQ) {
        float s = 0.f;
        const float4* p = (const float4*)&g_ldp[(size_t)b * NT2];
#pragma unroll
        for (int i = 0; i < NT2 / 4; ++i) {
            float4 v = p[i];
            s += v.x + v.y + v.z + v.w;
        }
        dout[(size_t)BQ * 1024 + b] = logd[b] - s;
    }
}

// ---------------- launch -----------------------------------------------------
extern "C" void kernel_launch(void* const* d_in, const int* in_sizes, int n_in,
                              void* d_out, int out_size)
{
    const float* v_in = (const float*)d_in[0];
    const float* logd = (const float*)d_in[1];
    const float* W1   = (const float*)d_in[2];
    const float* b1   = (const float*)d_in[3];
    const float* W2   = (const float*)d_in[4];
    const float* b2   = (const float*)d_in[5];
    float* out = (float*)d_out;

    cudaFuncSetAttribute(k_gemm1_tc, cudaFuncAttributeMaxDynamicSharedMemorySize, DYNSMEM);
    cudaFuncSetAttribute(k_gemm2_tc, cudaFuncAttributeMaxDynamicSharedMemorySize, DYNSMEM);

    k_prep_a1<<<(BQ * 128 + 255) / 256, 256>>>(v_in, out);
    k_prep_w1<<<dim3(16, 16),  dim3(32, 8)>>>(W1);
    k_prep_w2<<<dim3(256, 16), dim3(32, 8)>>>(W2);
    k_gemm1_tc<<<dim3(2, 64),  256, DYNSMEM>>>(b1);
    k_gemm2_tc<<<dim3(32, 64), 256, DYNSMEM>>>(v_in, b2, out);
    k_finalize<<<32, 256>>>(logd, out);
}

// round 6
// speedup vs baseline: 1.5141x; 1.5141x over previous
#include <cuda_runtime.h>
#include <cuda_bf16.h>
#include <cstdint>

#define BQ 8192
#define HDIM 512
#define HK 8192
#define NT2 64               // gemm2 n-tiles = 8192/128
#define NC 16                // k-chunks: 2 segments (a_hi, a_lo) x (512/64)
#define STAGE_BYTES 32768    // A 16KB + B 16KB
#define SMEM_RED 98304       // after 3 stages
#define DYNSMEM 102400

// ---------------- device scratch (no cudaMalloc allowed) -------------------
__device__ __align__(16) __nv_bfloat16 g_a1h[BQ*HDIM];
__device__ __align__(16) __nv_bfloat16 g_a1l[BQ*HDIM];
__device__ __align__(16) __nv_bfloat16 g_hh [BQ*HDIM];
__device__ __align__(16) __nv_bfloat16 g_hl [BQ*HDIM];
__device__ __align__(16) __nv_bfloat16 g_w1h[HDIM*HDIM];
__device__ __align__(16) __nv_bfloat16 g_w2h[(size_t)HK*HDIM];
__device__ float g_ldp[(size_t)BQ*NT2];

// ---------------- helpers ---------------------------------------------------
__device__ __forceinline__ uint32_t smem_u32(const void* p){
    uint32_t a;
    asm("{ .reg .u64 t; cvta.to.shared.u64 t, %1; cvt.u32.u64 %0, t; }" : "=r"(a) : "l"(p));
    return a;
}
__device__ __forceinline__ void cp16(uint32_t dst, const void* src){
    asm volatile("cp.async.cg.shared.global [%0], [%1], 16;" :: "r"(dst), "l"(src));
}
__device__ __forceinline__ void cp_commit(){
    asm volatile("cp.async.commit_group;" ::: "memory");
}
template<int N> __device__ __forceinline__ void cp_wait(){
    asm volatile("cp.async.wait_group %0;" :: "n"(N) : "memory");
}
__device__ __forceinline__ void ldsm4(uint32_t* r, uint32_t addr){
    asm volatile("ldmatrix.sync.aligned.m8n8.x4.shared.b16 {%0,%1,%2,%3}, [%4];"
        : "=r"(r[0]), "=r"(r[1]), "=r"(r[2]), "=r"(r[3]) : "r"(addr));
}
__device__ __forceinline__ void mma16816(float* d, const uint32_t* a, const uint32_t* b){
    asm volatile("mma.sync.aligned.m16n8k16.row.col.f32.bf16.bf16.f32 "
        "{%0,%1,%2,%3},{%4,%5,%6,%7},{%8,%9},{%0,%1,%2,%3};"
        : "+f"(d[0]), "+f"(d[1]), "+f"(d[2]), "+f"(d[3])
        : "r"(a[0]), "r"(a[1]), "r"(a[2]), "r"(a[3]), "r"(b[0]), "r"(b[1]));
}
__device__ __forceinline__ float fast_tanh(float x){
    x = fminf(fmaxf(x, -15.f), 15.f);
    float e = __expf(2.f * x);
    return __fdividef(e - 1.f, e + 1.f);
}

// ---------------- mainloop --------------------------------------------------
// A: [rows, 512] bf16 hi/lo (k contiguous). B: Wt [Ntot, 512] bf16 (hi only).
// Result C[128][128] fp32 staged into smem at Csmem (stride 132).
__device__ __forceinline__ void issue_chunk(
    int c, uint32_t sbase,
    const __nv_bfloat16* __restrict__ ah, const __nv_bfloat16* __restrict__ al,
    const __nv_bfloat16* __restrict__ bh,
    int row0, int n0, int tid)
{
    const int seg = c >> 3;              // 0: a_hi, 1: a_lo
    const int kk  = (c & 7) << 6;
    const __nv_bfloat16* a = (seg == 1) ? al : ah;
    uint32_t abase = sbase, bbase = sbase + 16384;
#pragma unroll
    for (int j = 0; j < 4; ++j) {                // A: 128 rows x 128B
        int i = tid + 256 * j;
        int r = i >> 3, q = i & 7;
        uint32_t sw = (uint32_t)(r * 128) + ((uint32_t)(q ^ (r & 7)) << 4);
        cp16(abase + sw, a + (size_t)(row0 + r) * HDIM + kk + q * 8);
    }
#pragma unroll
    for (int j = 0; j < 4; ++j) {                // B: 128 n-rows x 128B
        int i = tid + 256 * j;
        int r = i >> 3, q = i & 7;
        uint32_t sw = (uint32_t)(r * 128) + ((uint32_t)(q ^ (r & 7)) << 4);
        cp16(bbase + sw, bh + (size_t)(n0 + r) * HDIM + kk + q * 8);
    }
    cp_commit();
}

__device__ __forceinline__ void gemm_mainloop(
    const __nv_bfloat16* ah, const __nv_bfloat16* al,
    const __nv_bfloat16* bh,
    int row0, int n0, char* dsm, float* Csmem)
{
    const int tid  = threadIdx.x;
    const int wid  = tid >> 5;
    const int lane = tid & 31;
    const int wm   = wid & 1;          // 0/1 -> 64-row half
    const int wn   = wid >> 1;         // 0..3 -> 32-col quarter
    const uint32_t sb = smem_u32(dsm);

    float acc[4][4][4];
#pragma unroll
    for (int mi = 0; mi < 4; ++mi)
#pragma unroll
        for (int ni = 0; ni < 4; ++ni)
#pragma unroll
            for (int q = 0; q < 4; ++q) acc[mi][ni][q] = 0.f;

    const int arow = wm * 64 + (lane & 15);
    const int ahl  = lane >> 4;
    const int brow = wn * 32 + (lane & 7) + ((lane >> 4) << 3);
    const int bhl  = (lane >> 3) & 1;

    issue_chunk(0, sb,               ah, al, bh, row0, n0, tid);
    issue_chunk(1, sb + STAGE_BYTES, ah, al, bh, row0, n0, tid);

    for (int i = 0; i < NC; ++i) {
        if (i + 2 < NC) {
            issue_chunk(i + 2, sb + (uint32_t)((i + 2) % 3) * STAGE_BYTES,
                        ah, al, bh, row0, n0, tid);
            cp_wait<2>();
        } else {
            cp_wait<0>();
        }
        __syncthreads();

        uint32_t ab = sb + (uint32_t)(i % 3) * STAGE_BYTES;
        uint32_t bb = ab + 16384;
#pragma unroll
        for (int ks = 0; ks < 4; ++ks) {
            uint32_t af[4][4], bf[2][4];
#pragma unroll
            for (int mi = 0; mi < 4; ++mi) {
                int r = arow + mi * 16;
                uint32_t addr = ab + (uint32_t)(r * 128)
                              + ((uint32_t)((ks * 2 + ahl) ^ (r & 7)) << 4);
                ldsm4(af[mi], addr);
            }
#pragma unroll
            for (int bi = 0; bi < 2; ++bi) {
                int r = brow + bi * 16;
                uint32_t addr = bb + (uint32_t)(r * 128)
                              + ((uint32_t)((ks * 2 + bhl) ^ (r & 7)) << 4);
                ldsm4(bf[bi], addr);
            }
#pragma unroll
            for (int mi = 0; mi < 4; ++mi)
#pragma unroll
                for (int ni = 0; ni < 4; ++ni)
                    mma16816(acc[mi][ni], af[mi], &bf[ni >> 1][(ni & 1) * 2]);
        }
        __syncthreads();
    }

    // stage C to smem (aliases stage buffers; all compute done + barrier above)
    const int gid = lane >> 2;
    const int c0  = wn * 32 + (lane & 3) * 2;
#pragma unroll
    for (int mi = 0; mi < 4; ++mi) {
        int r = wm * 64 + mi * 16 + gid;
#pragma unroll
        for (int ni = 0; ni < 4; ++ni) {
            float2 lo = make_float2(acc[mi][ni][0], acc[mi][ni][1]);
            float2 hi = make_float2(acc[mi][ni][2], acc[mi][ni][3]);
            *(float2*)&Csmem[(size_t)r * 132 + c0 + ni * 8]       = lo;
            *(float2*)&Csmem[(size_t)(r + 8) * 132 + c0 + ni * 8] = hi;
        }
    }
    __syncthreads();
}

// ---------------- GEMM1: h = tanh((v_p-0.5)@W1+b1) -> bf16 hi/lo ------------
__global__ __launch_bounds__(256, 2) void k_gemm1_tc(const float* __restrict__ b1)
{
    extern __shared__ char dsm[];
    float* Csmem = (float*)dsm;
    const int row0 = blockIdx.y * 128;
    const int n0   = blockIdx.x * 128;

    gemm_mainloop(g_a1h, g_a1l, g_w1h, row0, n0, dsm, Csmem);

    const int tid = threadIdx.x;
    const int r   = tid >> 1;
    const int ch  = (tid & 1) * 64;
    const int row = row0 + r;
#pragma unroll 4
    for (int c = 0; c < 64; c += 4) {
        float4 v = *(float4*)&Csmem[(size_t)r * 132 + ch + c];
        int cg = n0 + ch + c;
        float t0 = fast_tanh(v.x + b1[cg + 0]);
        float t1 = fast_tanh(v.y + b1[cg + 1]);
        float t2 = fast_tanh(v.z + b1[cg + 2]);
        float t3 = fast_tanh(v.w + b1[cg + 3]);
        __nv_bfloat16 h0 = __float2bfloat16(t0), h1 = __float2bfloat16(t1);
        __nv_bfloat16 h2 = __float2bfloat16(t2), h3 = __float2bfloat16(t3);
        __nv_bfloat162 ha; ha.x = h0; ha.y = h1;
        __nv_bfloat162 hb; hb.x = h2; hb.y = h3;
        __nv_bfloat162 la, lb;
        la.x = __float2bfloat16(t0 - __bfloat162float(h0));
        la.y = __float2bfloat16(t1 - __bfloat162float(h1));
        lb.x = __float2bfloat16(t2 - __bfloat162float(h2));
        lb.y = __float2bfloat16(t3 - __bfloat162float(h3));
        *(__nv_bfloat162*)&g_hh[(size_t)row * HDIM + cg]     = ha;
        *(__nv_bfloat162*)&g_hh[(size_t)row * HDIM + cg + 2] = hb;
        *(__nv_bfloat162*)&g_hl[(size_t)row * HDIM + cg]     = la;
        *(__nv_bfloat162*)&g_hl[(size_t)row * HDIM + cg + 2] = lb;
    }
}

// ---------------- GEMM2 fused: tanh->softmax(16)->spline->logp --------------
__global__ __launch_bounds__(256, 2) void k_gemm2_tc(
    const float* __restrict__ v_in, const float* __restrict__ b2,
    float* __restrict__ dout)
{
    extern __shared__ char dsm[];
    float* Csmem = (float*)dsm;
    float* red   = (float*)(dsm + SMEM_RED);        // [128][8]
    const int row0 = blockIdx.y * 128;
    const int n0   = blockIdx.x * 128;
    const int hbase = n0 >> 4;                      // 8 h per tile

    gemm_mainloop(g_hh, g_hl, g_w2h, row0, n0, dsm, Csmem);

    const int tid = threadIdx.x;
#pragma unroll 1
    for (int p = 0; p < 4; ++p) {
        int idx = p * 256 + tid;          // 1024 (row, group) pairs
        int r = idx >> 3, g = idx & 7;
        float e[16]; float sum = 0.f;
        const float* crow = &Csmem[(size_t)r * 132 + g * 16];
#pragma unroll
        for (int j4 = 0; j4 < 4; ++j4) {
            float4 cv = *(const float4*)&crow[j4 * 4];
            float t0 = fast_tanh(cv.x + b2[n0 + g * 16 + j4 * 4 + 0]);
            float t1 = fast_tanh(cv.y + b2[n0 + g * 16 + j4 * 4 + 1]);
            float t2 = fast_tanh(cv.z + b2[n0 + g * 16 + j4 * 4 + 2]);
            float t3 = fast_tanh(cv.w + b2[n0 + g * 16 + j4 * 4 + 3]);
            e[j4*4+0] = __expf(t0); e[j4*4+1] = __expf(t1);
            e[j4*4+2] = __expf(t2); e[j4*4+3] = __expf(t3);
            sum += e[j4*4+0] + e[j4*4+1] + e[j4*4+2] + e[j4*4+3];
        }
        int h = hbase + g;
        float v = v_in[(size_t)(row0 + r) * 1024 + 512 + h];
        int kk = (int)(v * 16.f); kk = kk < 0 ? 0 : (kk > 15 ? 15 : kk);
        float pref = 0.f, pk = 0.f;
#pragma unroll
        for (int j = 0; j < 16; ++j) {
            if (j < kk)  pref += e[j];
            if (j == kk) pk = e[j];
        }
        float inv   = __fdividef(1.f, sum);
        float p_k   = pk * inv;
        float ylo   = pref * inv;
        float alpha = v * 16.f - (float)kk;
        dout[(size_t)(row0 + r) * 1024 + 512 + h] = ylo + alpha * p_k;
        red[r * 8 + g] = __logf(p_k);
    }
    __syncthreads();
    if (tid < 128) {
        float s = 0.f;
#pragma unroll
        for (int g = 0; g < 8; ++g) s += red[tid * 8 + g];
        g_ldp[(size_t)(row0 + tid) * NT2 + blockIdx.x] = s;
    }
}

// ---------------- prep + finalize -------------------------------------------
__global__ __launch_bounds__(256) void k_prep_a1(const float* __restrict__ v_in,
                                                 float* __restrict__ out)
{
    int i = blockIdx.x * 256 + threadIdx.x;          // float4 over [BQ,128]
    if (i >= BQ * 128) return;
    int row = i >> 7, c4 = i & 127;
    float4 v = ((const float4*)v_in)[(size_t)row * 256 + c4];
    ((float4*)out)[(size_t)row * 256 + c4] = v;       // passive copy
    float a[4] = {v.x - 0.5f, v.y - 0.5f, v.z - 0.5f, v.w - 0.5f};
    __nv_bfloat162 h2[2], l2[2];
#pragma unroll
    for (int p = 0; p < 2; ++p) {
        __nv_bfloat16 h0 = __float2bfloat16(a[2*p]), h1 = __float2bfloat16(a[2*p+1]);
        h2[p].x = h0; h2[p].y = h1;
        l2[p].x = __float2bfloat16(a[2*p]   - __bfloat162float(h0));
        l2[p].y = __float2bfloat16(a[2*p+1] - __bfloat162float(h1));
    }
    __nv_bfloat162* ph = (__nv_bfloat162*)&g_a1h[(size_t)row * HDIM + c4 * 4];
    __nv_bfloat162* pl = (__nv_bfloat162*)&g_a1l[(size_t)row * HDIM + c4 * 4];
    ph[0] = h2[0]; ph[1] = h2[1];
    pl[0] = l2[0]; pl[1] = l2[1];
}

__device__ __forceinline__ void prep_wt_body(
    const float* __restrict__ W, __nv_bfloat16* th, int N)
{
    __shared__ float t[32][33];
    int n0 = blockIdx.x * 32, k0 = blockIdx.y * 32;
    int tx = threadIdx.x, ty = threadIdx.y;
#pragma unroll
    for (int i = 0; i < 4; ++i)
        t[ty + 8 * i][tx] = W[(size_t)(k0 + ty + 8 * i) * N + n0 + tx];
    __syncthreads();
#pragma unroll
    for (int i = 0; i < 4; ++i) {
        float v = t[tx][ty + 8 * i];
        th[(size_t)(n0 + ty + 8 * i) * HDIM + k0 + tx] = __float2bfloat16(v);
    }
}
__global__ void k_prep_w1(const float* __restrict__ W){ prep_wt_body(W, g_w1h, HDIM); }
__global__ void k_prep_w2(const float* __restrict__ W){ prep_wt_body(W, g_w2h, HK);   }

__global__ __launch_bounds__(256) void k_finalize(const float* __restrict__ logd,
                                                  float* __restrict__ dout)
{
    int b = blockIdx.x * 256 + threadIdx.x;
    if (b < BQ) {
        float s = 0.f;
        const float4* p = (const float4*)&g_ldp[(size_t)b * NT2];
#pragma unroll
        for (int i = 0; i < NT2 / 4; ++i) {
            float4 v = p[i];
            s += v.x + v.y + v.z + v.w;
        }
        dout[(size_t)BQ * 1024 + b] = logd[b] - s;
    }
}

// ---------------- launch -----------------------------------------------------
extern "C" void kernel_launch(void* const* d_in, const int* in_sizes, int n_in,
                              void* d_out, int out_size)
{
    const float* v_in = (const float*)d_in[0];
    const float* logd = (const float*)d_in[1];
    const float* W1   = (const float*)d_in[2];
    const float* b1   = (const float*)d_in[3];
    const float* W2   = (const float*)d_in[4];
    const float* b2   = (const float*)d_in[5];
    float* out = (float*)d_out;

    cudaFuncSetAttribute(k_gemm1_tc, cudaFuncAttributeMaxDynamicSharedMemorySize, DYNSMEM);
    cudaFuncSetAttribute(k_gemm2_tc, cudaFuncAttributeMaxDynamicSharedMemorySize, DYNSMEM);

    k_prep_a1<<<(BQ * 128 + 255) / 256, 256>>>(v_in, out);
    k_prep_w1<<<dim3(16, 16),  dim3(32, 8)>>>(W1);
    k_prep_w2<<<dim3(256, 16), dim3(32, 8)>>>(W2);
    k_gemm1_tc<<<dim3(4, 64),  256, DYNSMEM>>>(b1);
    k_gemm2_tc<<<dim3(64, 64), 256, DYNSMEM>>>(v_in, b2, out);
    k_finalize<<<32, 256>>>(logd, out);
}

// round 7
// speedup vs baseline: 1.6055x; 1.0603x over previous
#include <cuda_runtime.h>
#include <cuda_bf16.h>
#include <cstdint>

#define BQ 8192
#define HDIM 512
#define HK 8192
#define NT2 64               // gemm2 n-tiles = 8192/128
#define NC2 8                // k chunk-pairs: 512/64 (each pair = a_hi + a_lo vs same B)
#define STAGE_BYTES 49152    // A_hi 16K + A_lo 16K + B 16K
#define DYNSMEM 98304        // 2 stages
#define CSTRIDE 132

// ---------------- device scratch (no cudaMalloc allowed) -------------------
__device__ __align__(16) __nv_bfloat16 g_a1h[BQ*HDIM];
__device__ __align__(16) __nv_bfloat16 g_a1l[BQ*HDIM];
__device__ __align__(16) __nv_bfloat16 g_hh [BQ*HDIM];
__device__ __align__(16) __nv_bfloat16 g_hl [BQ*HDIM];
__device__ __align__(16) __nv_bfloat16 g_w1h[HDIM*HDIM];
__device__ __align__(16) __nv_bfloat16 g_w2h[(size_t)HK*HDIM];
__device__ float g_ldp[(size_t)BQ*NT2];

// ---------------- helpers ---------------------------------------------------
__device__ __forceinline__ uint32_t smem_u32(const void* p){
    uint32_t a;
    asm("{ .reg .u64 t; cvta.to.shared.u64 t, %1; cvt.u32.u64 %0, t; }" : "=r"(a) : "l"(p));
    return a;
}
__device__ __forceinline__ void cp16(uint32_t dst, const void* src){
    asm volatile("cp.async.cg.shared.global [%0], [%1], 16;" :: "r"(dst), "l"(src));
}
__device__ __forceinline__ void cp_commit(){
    asm volatile("cp.async.commit_group;" ::: "memory");
}
template<int N> __device__ __forceinline__ void cp_wait(){
    asm volatile("cp.async.wait_group %0;" :: "n"(N) : "memory");
}
__device__ __forceinline__ void ldsm4(uint32_t* r, uint32_t addr){
    asm volatile("ldmatrix.sync.aligned.m8n8.x4.shared.b16 {%0,%1,%2,%3}, [%4];"
        : "=r"(r[0]), "=r"(r[1]), "=r"(r[2]), "=r"(r[3]) : "r"(addr));
}
__device__ __forceinline__ void mma16816(float* d, const uint32_t* a, const uint32_t* b){
    asm volatile("mma.sync.aligned.m16n8k16.row.col.f32.bf16.bf16.f32 "
        "{%0,%1,%2,%3},{%4,%5,%6,%7},{%8,%9},{%0,%1,%2,%3};"
        : "+f"(d[0]), "+f"(d[1]), "+f"(d[2]), "+f"(d[3])
        : "r"(a[0]), "r"(a[1]), "r"(a[2]), "r"(a[3]), "r"(b[0]), "r"(b[1]));
}
__device__ __forceinline__ float fast_tanh(float x){
    x = fminf(fmaxf(x, -15.f), 15.f);
    float e = __expf(2.f * x);
    return __fdividef(e - 1.f, e + 1.f);
}

// ---------------- mainloop --------------------------------------------------
// Chunk-pair c (k64 window): stages A_hi, A_lo, B once; both A segments hit the
// same B tile and accumulate into the same accumulators.
__device__ __forceinline__ void issue_chunk(
    int c, uint32_t sbase,
    const __nv_bfloat16* __restrict__ ah, const __nv_bfloat16* __restrict__ al,
    const __nv_bfloat16* __restrict__ bh,
    int row0, int n0, int tid)
{
    const int kk = c << 6;
#pragma unroll
    for (int j = 0; j < 4; ++j) {                // A_hi: 128 rows x 128B
        int i = tid + 256 * j;
        int r = i >> 3, q = i & 7;
        uint32_t sw = (uint32_t)(r * 128) + ((uint32_t)(q ^ (r & 7)) << 4);
        cp16(sbase + sw, ah + (size_t)(row0 + r) * HDIM + kk + q * 8);
    }
#pragma unroll
    for (int j = 0; j < 4; ++j) {                // A_lo: 128 rows x 128B
        int i = tid + 256 * j;
        int r = i >> 3, q = i & 7;
        uint32_t sw = (uint32_t)(r * 128) + ((uint32_t)(q ^ (r & 7)) << 4);
        cp16(sbase + 16384u + sw, al + (size_t)(row0 + r) * HDIM + kk + q * 8);
    }
#pragma unroll
    for (int j = 0; j < 4; ++j) {                // B: 128 n-rows x 128B
        int i = tid + 256 * j;
        int r = i >> 3, q = i & 7;
        uint32_t sw = (uint32_t)(r * 128) + ((uint32_t)(q ^ (r & 7)) << 4);
        cp16(sbase + 32768u + sw, bh + (size_t)(n0 + r) * HDIM + kk + q * 8);
    }
    cp_commit();
}

__device__ __forceinline__ void gemm_mainloop(
    const __nv_bfloat16* ah, const __nv_bfloat16* al,
    const __nv_bfloat16* bh,
    int row0, int n0, char* dsm, float* Csmem)
{
    const int tid  = threadIdx.x;
    const int wid  = tid >> 5;
    const int lane = tid & 31;
    const int wm   = wid & 1;          // 0/1 -> 64-row half
    const int wn   = wid >> 1;         // 0..3 -> 32-col quarter
    const uint32_t sb = smem_u32(dsm);

    float acc[4][4][4];
#pragma unroll
    for (int mi = 0; mi < 4; ++mi)
#pragma unroll
        for (int ni = 0; ni < 4; ++ni)
#pragma unroll
            for (int q = 0; q < 4; ++q) acc[mi][ni][q] = 0.f;

    const int arow = wm * 64 + (lane & 15);
    const int ahl  = lane >> 4;
    const int brow = wn * 32 + (lane & 7) + ((lane >> 4) << 3);
    const int bhl  = (lane >> 3) & 1;

    issue_chunk(0, sb,               ah, al, bh, row0, n0, tid);
    issue_chunk(1, sb + STAGE_BYTES, ah, al, bh, row0, n0, tid);

    for (int i = 0; i < NC2; ++i) {
        if (i + 2 < NC2) cp_wait<1>();
        else             cp_wait<0>();
        __syncthreads();

        uint32_t st = sb + (uint32_t)(i & 1) * STAGE_BYTES;
        uint32_t bb = st + 32768u;
#pragma unroll
        for (int ks = 0; ks < 4; ++ks) {
            uint32_t bf[2][4];
#pragma unroll
            for (int bi = 0; bi < 2; ++bi) {
                int r = brow + bi * 16;
                uint32_t addr = bb + (uint32_t)(r * 128)
                              + ((uint32_t)((ks * 2 + bhl) ^ (r & 7)) << 4);
                ldsm4(bf[bi], addr);
            }
            uint32_t afh[4][4];
#pragma unroll
            for (int mi = 0; mi < 4; ++mi) {
                int r = arow + mi * 16;
                uint32_t addr = st + (uint32_t)(r * 128)
                              + ((uint32_t)((ks * 2 + ahl) ^ (r & 7)) << 4);
                ldsm4(afh[mi], addr);
            }
#pragma unroll
            for (int mi = 0; mi < 4; ++mi)
#pragma unroll
                for (int ni = 0; ni < 4; ++ni)
                    mma16816(acc[mi][ni], afh[mi], &bf[ni >> 1][(ni & 1) * 2]);
            uint32_t afl[4][4];
#pragma unroll
            for (int mi = 0; mi < 4; ++mi) {
                int r = arow + mi * 16;
                uint32_t addr = st + 16384u + (uint32_t)(r * 128)
                              + ((uint32_t)((ks * 2 + ahl) ^ (r & 7)) << 4);
                ldsm4(afl[mi], addr);
            }
#pragma unroll
            for (int mi = 0; mi < 4; ++mi)
#pragma unroll
                for (int ni = 0; ni < 4; ++ni)
                    mma16816(acc[mi][ni], afl[mi], &bf[ni >> 1][(ni & 1) * 2]);
        }
        __syncthreads();
        int j = i + 2;
        if (j < NC2)
            issue_chunk(j, sb + (uint32_t)(j & 1) * STAGE_BYTES,
                        ah, al, bh, row0, n0, tid);
    }

    // stage C to smem (all compute done; last barrier above ensures reads done)
    const int gid = lane >> 2;
    const int c0  = wn * 32 + (lane & 3) * 2;
#pragma unroll
    for (int mi = 0; mi < 4; ++mi) {
        int r = wm * 64 + mi * 16 + gid;
#pragma unroll
        for (int ni = 0; ni < 4; ++ni) {
            *(float2*)&Csmem[(size_t)r * CSTRIDE + c0 + ni * 8] =
                make_float2(acc[mi][ni][0], acc[mi][ni][1]);
            *(float2*)&Csmem[(size_t)(r + 8) * CSTRIDE + c0 + ni * 8] =
                make_float2(acc[mi][ni][2], acc[mi][ni][3]);
        }
    }
    __syncthreads();
}

// ---------------- GEMM1: h = tanh((v_p-0.5)@W1+b1) -> bf16 hi/lo ------------
__global__ __launch_bounds__(256, 2) void k_gemm1_tc(const float* __restrict__ b1)
{
    extern __shared__ char dsm[];
    float* Csmem = (float*)dsm;
    const int row0 = blockIdx.y * 128;
    const int n0   = blockIdx.x * 128;

    gemm_mainloop(g_a1h, g_a1l, g_w1h, row0, n0, dsm, Csmem);

    const int tid = threadIdx.x;
    const int r   = tid >> 1;
    const int ch  = (tid & 1) * 64;
    const int row = row0 + r;
#pragma unroll 4
    for (int c = 0; c < 64; c += 4) {
        float4 v = *(float4*)&Csmem[(size_t)r * CSTRIDE + ch + c];
        int cg = n0 + ch + c;
        float t0 = fast_tanh(v.x + b1[cg + 0]);
        float t1 = fast_tanh(v.y + b1[cg + 1]);
        float t2 = fast_tanh(v.z + b1[cg + 2]);
        float t3 = fast_tanh(v.w + b1[cg + 3]);
        __nv_bfloat16 h0 = __float2bfloat16(t0), h1 = __float2bfloat16(t1);
        __nv_bfloat16 h2 = __float2bfloat16(t2), h3 = __float2bfloat16(t3);
        __nv_bfloat162 ha; ha.x = h0; ha.y = h1;
        __nv_bfloat162 hb; hb.x = h2; hb.y = h3;
        __nv_bfloat162 la, lb;
        la.x = __float2bfloat16(t0 - __bfloat162float(h0));
        la.y = __float2bfloat16(t1 - __bfloat162float(h1));
        lb.x = __float2bfloat16(t2 - __bfloat162float(h2));
        lb.y = __float2bfloat16(t3 - __bfloat162float(h3));
        *(__nv_bfloat162*)&g_hh[(size_t)row * HDIM + cg]     = ha;
        *(__nv_bfloat162*)&g_hh[(size_t)row * HDIM + cg + 2] = hb;
        *(__nv_bfloat162*)&g_hl[(size_t)row * HDIM + cg]     = la;
        *(__nv_bfloat162*)&g_hl[(size_t)row * HDIM + cg + 2] = lb;
    }
}

// ---------------- GEMM2 fused: tanh->softmax(16)->spline->logp --------------
__global__ __launch_bounds__(256, 2) void k_gemm2_tc(
    const float* __restrict__ v_in, const float* __restrict__ b2,
    float* __restrict__ dout)
{
    extern __shared__ char dsm[];
    float* Csmem = (float*)dsm;
    float* red   = (float*)(dsm + 128 * CSTRIDE * 4);   // [128][8] after C
    const int row0 = blockIdx.y * 128;
    const int n0   = blockIdx.x * 128;
    const int hbase = n0 >> 4;                      // 8 h per tile

    gemm_mainloop(g_hh, g_hl, g_w2h, row0, n0, dsm, Csmem);

    const int tid = threadIdx.x;
#pragma unroll 1
    for (int p = 0; p < 4; ++p) {
        int idx = p * 256 + tid;          // 1024 (row, group) pairs
        int r = idx >> 3, g = idx & 7;
        float e[16]; float sum = 0.f;
        const float* crow = &Csmem[(size_t)r * CSTRIDE + g * 16];
#pragma unroll
        for (int j4 = 0; j4 < 4; ++j4) {
            float4 cv = *(const float4*)&crow[j4 * 4];
            float t0 = fast_tanh(cv.x + b2[n0 + g * 16 + j4 * 4 + 0]);
            float t1 = fast_tanh(cv.y + b2[n0 + g * 16 + j4 * 4 + 1]);
            float t2 = fast_tanh(cv.z + b2[n0 + g * 16 + j4 * 4 + 2]);
            float t3 = fast_tanh(cv.w + b2[n0 + g * 16 + j4 * 4 + 3]);
            e[j4*4+0] = __expf(t0); e[j4*4+1] = __expf(t1);
            e[j4*4+2] = __expf(t2); e[j4*4+3] = __expf(t3);
            sum += e[j4*4+0] + e[j4*4+1] + e[j4*4+2] + e[j4*4+3];
        }
        int h = hbase + g;
        float v = v_in[(size_t)(row0 + r) * 1024 + 512 + h];
        int kk = (int)(v * 16.f); kk = kk < 0 ? 0 : (kk > 15 ? 15 : kk);
        float pref = 0.f, pk = 0.f;
#pragma unroll
        for (int j = 0; j < 16; ++j) {
            if (j < kk)  pref += e[j];
            if (j == kk) pk = e[j];
        }
        float inv   = __fdividef(1.f, sum);
        float p_k   = pk * inv;
        float ylo   = pref * inv;
        float alpha = v * 16.f - (float)kk;
        dout[(size_t)(row0 + r) * 1024 + 512 + h] = ylo + alpha * p_k;
        red[r * 8 + g] = __logf(p_k);
    }
    __syncthreads();
    if (tid < 128) {
        float s = 0.f;
#pragma unroll
        for (int g = 0; g < 8; ++g) s += red[tid * 8 + g];
        g_ldp[(size_t)(row0 + tid) * NT2 + blockIdx.x] = s;
    }
}

// ---------------- prep + finalize -------------------------------------------
__global__ __launch_bounds__(256) void k_prep_a1(const float* __restrict__ v_in,
                                                 float* __restrict__ out)
{
    int i = blockIdx.x * 256 + threadIdx.x;          // float4 over [BQ,128]
    if (i >= BQ * 128) return;
    int row = i >> 7, c4 = i & 127;
    float4 v = ((const float4*)v_in)[(size_t)row * 256 + c4];
    ((float4*)out)[(size_t)row * 256 + c4] = v;       // passive copy
    float a[4] = {v.x - 0.5f, v.y - 0.5f, v.z - 0.5f, v.w - 0.5f};
    __nv_bfloat162 h2[2], l2[2];
#pragma unroll
    for (int p = 0; p < 2; ++p) {
        __nv_bfloat16 h0 = __float2bfloat16(a[2*p]), h1 = __float2bfloat16(a[2*p+1]);
        h2[p].x = h0; h2[p].y = h1;
        l2[p].x = __float2bfloat16(a[2*p]   - __bfloat162float(h0));
        l2[p].y = __float2bfloat16(a[2*p+1] - __bfloat162float(h1));
    }
    __nv_bfloat162* ph = (__nv_bfloat162*)&g_a1h[(size_t)row * HDIM + c4 * 4];
    __nv_bfloat162* pl = (__nv_bfloat162*)&g_a1l[(size_t)row * HDIM + c4 * 4];
    ph[0] = h2[0]; ph[1] = h2[1];
    pl[0] = l2[0]; pl[1] = l2[1];
}

__device__ __forceinline__ void prep_wt_body(
    const float* __restrict__ W, __nv_bfloat16* th, int N)
{
    __shared__ float t[32][33];
    int n0 = blockIdx.x * 32, k0 = blockIdx.y * 32;
    int tx = threadIdx.x, ty = threadIdx.y;
#pragma unroll
    for (int i = 0; i < 4; ++i)
        t[ty + 8 * i][tx] = W[(size_t)(k0 + ty + 8 * i) * N + n0 + tx];
    __syncthreads();
#pragma unroll
    for (int i = 0; i < 4; ++i) {
        float v = t[tx][ty + 8 * i];
        th[(size_t)(n0 + ty + 8 * i) * HDIM + k0 + tx] = __float2bfloat16(v);
    }
}
__global__ void k_prep_w1(const float* __restrict__ W){ prep_wt_body(W, g_w1h, HDIM); }
__global__ void k_prep_w2(const float* __restrict__ W){ prep_wt_body(W, g_w2h, HK);   }

__global__ __launch_bounds__(256) void k_finalize(const float* __restrict__ logd,
                                                  float* __restrict__ dout)
{
    int b = blockIdx.x * 256 + threadIdx.x;
    if (b < BQ) {
        float s = 0.f;
        const float4* p = (const float4*)&g_ldp[(size_t)b * NT2];
#pragma unroll
        for (int i = 0; i < NT2 / 4; ++i) {
            float4 v = p[i];
            s += v.x + v.y + v.z + v.w;
        }
        dout[(size_t)BQ * 1024 + b] = logd[b] - s;
    }
}

// ---------------- launch -----------------------------------------------------
extern "C" void kernel_launch(void* const* d_in, const int* in_sizes, int n_in,
                              void* d_out, int out_size)
{
    const float* v_in = (const float*)d_in[0];
    const float* logd = (const float*)d_in[1];
    const float* W1   = (const float*)d_in[2];
    const float* b1   = (const float*)d_in[3];
    const float* W2   = (const float*)d_in[4];
    const float* b2   = (const float*)d_in[5];
    float* out = (float*)d_out;

    cudaFuncSetAttribute(k_gemm1_tc, cudaFuncAttributeMaxDynamicSharedMemorySize, DYNSMEM);
    cudaFuncSetAttribute(k_gemm2_tc, cudaFuncAttributeMaxDynamicSharedMemorySize, DYNSMEM);

    k_prep_a1<<<(BQ * 128 + 255) / 256, 256>>>(v_in, out);
    k_prep_w1<<<dim3(16, 16),  dim3(32, 8)>>>(W1);
    k_prep_w2<<<dim3(256, 16), dim3(32, 8)>>>(W2);
    k_gemm1_tc<<<dim3(4, 64),  256, DYNSMEM>>>(b1);
    k_gemm2_tc<<<dim3(64, 64), 256, DYNSMEM>>>(v_in, b2, out);
    k_finalize<<<32, 256>>>(logd, out);
}

// round 8
// speedup vs baseline: 2.4230x; 1.5092x over previous
#include <cuda_runtime.h>
#include <cuda_bf16.h>
#include <cuda_fp16.h>
#include <cstdint>

#define BQ 8192
#define HDIM 512
#define HK 8192
#define NT2 64               // gemm2 n-tiles = 8192/128
#define NC 8                 // k chunks of 64 (single fp16 pass)
#define STAGE_BYTES 32768    // A 16K + B 16K
#define DYNSMEM 98304        // 3 stages
#define CSTRIDE 132

// ---------------- device scratch (no cudaMalloc allowed) -------------------
__device__ __align__(16) __half g_a1[BQ*HDIM];
__device__ __align__(16) __half g_h [BQ*HDIM];
__device__ __align__(16) __half g_w1[HDIM*HDIM];
__device__ __align__(16) __half g_w2[(size_t)HK*HDIM];
__device__ float g_ldp[(size_t)BQ*NT2];

// ---------------- helpers ---------------------------------------------------
__device__ __forceinline__ uint32_t smem_u32(const void* p){
    uint32_t a;
    asm("{ .reg .u64 t; cvta.to.shared.u64 t, %1; cvt.u32.u64 %0, t; }" : "=r"(a) : "l"(p));
    return a;
}
__device__ __forceinline__ void cp16(uint32_t dst, const void* src){
    asm volatile("cp.async.cg.shared.global [%0], [%1], 16;" :: "r"(dst), "l"(src));
}
__device__ __forceinline__ void cp_commit(){
    asm volatile("cp.async.commit_group;" ::: "memory");
}
template<int N> __device__ __forceinline__ void cp_wait(){
    asm volatile("cp.async.wait_group %0;" :: "n"(N) : "memory");
}
__device__ __forceinline__ void ldsm4(uint32_t* r, uint32_t addr){
    asm volatile("ldmatrix.sync.aligned.m8n8.x4.shared.b16 {%0,%1,%2,%3}, [%4];"
        : "=r"(r[0]), "=r"(r[1]), "=r"(r[2]), "=r"(r[3]) : "r"(addr));
}
__device__ __forceinline__ void mma16816(float* d, const uint32_t* a, const uint32_t* b){
    asm volatile("mma.sync.aligned.m16n8k16.row.col.f32.f16.f16.f32 "
        "{%0,%1,%2,%3},{%4,%5,%6,%7},{%8,%9},{%0,%1,%2,%3};"
        : "+f"(d[0]), "+f"(d[1]), "+f"(d[2]), "+f"(d[3])
        : "r"(a[0]), "r"(a[1]), "r"(a[2]), "r"(a[3]), "r"(b[0]), "r"(b[1]));
}
__device__ __forceinline__ float fast_tanh(float x){
    x = fminf(fmaxf(x, -15.f), 15.f);
    float e = __expf(2.f * x);
    return __fdividef(e - 1.f, e + 1.f);
}

// ---------------- mainloop --------------------------------------------------
// Chunk c = k64 window. Stage: A 128x128B (16K) + B 128x128B (16K).
__device__ __forceinline__ void issue_chunk(
    int c, uint32_t sbase,
    const __half* __restrict__ a, const __half* __restrict__ b,
    int row0, int n0, int tid)
{
    const int kk = c << 6;
#pragma unroll
    for (int j = 0; j < 4; ++j) {                // A: 128 rows x 128B
        int i = tid + 256 * j;
        int r = i >> 3, q = i & 7;
        uint32_t sw = (uint32_t)(r * 128) + ((uint32_t)(q ^ (r & 7)) << 4);
        cp16(sbase + sw, a + (size_t)(row0 + r) * HDIM + kk + q * 8);
    }
#pragma unroll
    for (int j = 0; j < 4; ++j) {                // B: 128 n-rows x 128B
        int i = tid + 256 * j;
        int r = i >> 3, q = i & 7;
        uint32_t sw = (uint32_t)(r * 128) + ((uint32_t)(q ^ (r & 7)) << 4);
        cp16(sbase + 16384u + sw, b + (size_t)(n0 + r) * HDIM + kk + q * 8);
    }
    cp_commit();
}

__device__ __forceinline__ void gemm_mainloop(
    const __half* a, const __half* b,
    int row0, int n0, char* dsm, float* Csmem)
{
    const int tid  = threadIdx.x;
    const int wid  = tid >> 5;
    const int lane = tid & 31;
    const int wm   = wid & 1;          // 0/1 -> 64-row half
    const int wn   = wid >> 1;         // 0..3 -> 32-col quarter
    const uint32_t sb = smem_u32(dsm);

    float acc[4][4][4];
#pragma unroll
    for (int mi = 0; mi < 4; ++mi)
#pragma unroll
        for (int ni = 0; ni < 4; ++ni)
#pragma unroll
            for (int q = 0; q < 4; ++q) acc[mi][ni][q] = 0.f;

    const int arow = wm * 64 + (lane & 15);
    const int ahl  = lane >> 4;
    const int brow = wn * 32 + (lane & 7) + ((lane >> 4) << 3);
    const int bhl  = (lane >> 3) & 1;

    issue_chunk(0, sb,               a, b, row0, n0, tid);
    issue_chunk(1, sb + STAGE_BYTES, a, b, row0, n0, tid);

    for (int i = 0; i < NC; ++i) {
        if (i < NC - 1) cp_wait<1>();
        else            cp_wait<0>();
        __syncthreads();                 // stage i ready; stage (i-1)%3 drained

        int j = i + 2;                   // prefetch into slot (i+2)%3 == (i-1)%3
        if (j < NC) {
            uint32_t slot = (uint32_t)(j % 3) * STAGE_BYTES;
            issue_chunk(j, sb + slot, a, b, row0, n0, tid);
        }

        uint32_t st = sb + (uint32_t)(i % 3) * STAGE_BYTES;
        uint32_t bb = st + 16384u;
#pragma unroll
        for (int ks = 0; ks < 4; ++ks) {
            uint32_t bf[2][4];
#pragma unroll
            for (int bi = 0; bi < 2; ++bi) {
                int r = brow + bi * 16;
                uint32_t addr = bb + (uint32_t)(r * 128)
                              + ((uint32_t)((ks * 2 + bhl) ^ (r & 7)) << 4);
                ldsm4(bf[bi], addr);
            }
            uint32_t af[4][4];
#pragma unroll
            for (int mi = 0; mi < 4; ++mi) {
                int r = arow + mi * 16;
                uint32_t addr = st + (uint32_t)(r * 128)
                              + ((uint32_t)((ks * 2 + ahl) ^ (r & 7)) << 4);
                ldsm4(af[mi], addr);
            }
#pragma unroll
            for (int mi = 0; mi < 4; ++mi)
#pragma unroll
                for (int ni = 0; ni < 4; ++ni)
                    mma16816(acc[mi][ni], af[mi], &bf[ni >> 1][(ni & 1) * 2]);
        }
    }
    __syncthreads();   // all compute done before C staging overwrites stages

    const int gid = lane >> 2;
    const int c0  = wn * 32 + (lane & 3) * 2;
#pragma unroll
    for (int mi = 0; mi < 4; ++mi) {
        int r = wm * 64 + mi * 16 + gid;
#pragma unroll
        for (int ni = 0; ni < 4; ++ni) {
            *(float2*)&Csmem[(size_t)r * CSTRIDE + c0 + ni * 8] =
                make_float2(acc[mi][ni][0], acc[mi][ni][1]);
            *(float2*)&Csmem[(size_t)(r + 8) * CSTRIDE + c0 + ni * 8] =
                make_float2(acc[mi][ni][2], acc[mi][ni][3]);
        }
    }
    __syncthreads();
}

// ---------------- GEMM1: h = tanh((v_p-0.5)@W1+b1) -> fp16 ------------------
__global__ __launch_bounds__(256, 2) void k_gemm1_tc(const float* __restrict__ b1)
{
    extern __shared__ char dsm[];
    float* Csmem = (float*)dsm;
    const int row0 = blockIdx.y * 128;
    const int n0   = blockIdx.x * 128;

    gemm_mainloop(g_a1, g_w1, row0, n0, dsm, Csmem);

    const int tid = threadIdx.x;
    const int r   = tid >> 1;
    const int ch  = (tid & 1) * 64;
    const int row = row0 + r;
#pragma unroll 4
    for (int c = 0; c < 64; c += 4) {
        float4 v = *(float4*)&Csmem[(size_t)r * CSTRIDE + ch + c];
        int cg = n0 + ch + c;
        float t0 = fast_tanh(v.x + b1[cg + 0]);
        float t1 = fast_tanh(v.y + b1[cg + 1]);
        float t2 = fast_tanh(v.z + b1[cg + 2]);
        float t3 = fast_tanh(v.w + b1[cg + 3]);
        __half2 ha = __floats2half2_rn(t0, t1);
        __half2 hb = __floats2half2_rn(t2, t3);
        *(__half2*)&g_h[(size_t)row * HDIM + cg]     = ha;
        *(__half2*)&g_h[(size_t)row * HDIM + cg + 2] = hb;
    }
}

// ---------------- GEMM2 fused: tanh->softmax(16)->spline->logp --------------
__global__ __launch_bounds__(256, 2) void k_gemm2_tc(
    const float* __restrict__ v_in, const float* __restrict__ b2,
    float* __restrict__ dout)
{
    extern __shared__ char dsm[];
    float* Csmem = (float*)dsm;
    float* red   = (float*)(dsm + 128 * CSTRIDE * 4);   // [128][8] after C
    const int row0 = blockIdx.y * 128;
    const int n0   = blockIdx.x * 128;
    const int hbase = n0 >> 4;                      // 8 h per tile

    gemm_mainloop(g_h, g_w2, row0, n0, dsm, Csmem);

    const int tid = threadIdx.x;
#pragma unroll 1
    for (int p = 0; p < 4; ++p) {
        int idx = p * 256 + tid;          // 1024 (row, group) pairs
        int r = idx >> 3, g = idx & 7;
        float e[16]; float sum = 0.f;
        const float* crow = &Csmem[(size_t)r * CSTRIDE + g * 16];
#pragma unroll
        for (int j4 = 0; j4 < 4; ++j4) {
            float4 cv = *(const float4*)&crow[j4 * 4];
            float t0 = fast_tanh(cv.x + b2[n0 + g * 16 + j4 * 4 + 0]);
            float t1 = fast_tanh(cv.y + b2[n0 + g * 16 + j4 * 4 + 1]);
            float t2 = fast_tanh(cv.z + b2[n0 + g * 16 + j4 * 4 + 2]);
            float t3 = fast_tanh(cv.w + b2[n0 + g * 16 + j4 * 4 + 3]);
            e[j4*4+0] = __expf(t0); e[j4*4+1] = __expf(t1);
            e[j4*4+2] = __expf(t2); e[j4*4+3] = __expf(t3);
            sum += e[j4*4+0] + e[j4*4+1] + e[j4*4+2] + e[j4*4+3];
        }
        int h = hbase + g;
        float v = v_in[(size_t)(row0 + r) * 1024 + 512 + h];
        int kk = (int)(v * 16.f); kk = kk < 0 ? 0 : (kk > 15 ? 15 : kk);
        float pref = 0.f, pk = 0.f;
#pragma unroll
        for (int j = 0; j < 16; ++j) {
            if (j < kk)  pref += e[j];
            if (j == kk) pk = e[j];
        }
        float inv   = __fdividef(1.f, sum);
        float p_k   = pk * inv;
        float ylo   = pref * inv;
        float alpha = v * 16.f - (float)kk;
        dout[(size_t)(row0 + r) * 1024 + 512 + h] = ylo + alpha * p_k;
        red[r * 8 + g] = __logf(p_k);
    }
    __syncthreads();
    if (tid < 128) {
        float s = 0.f;
#pragma unroll
        for (int g = 0; g < 8; ++g) s += red[tid * 8 + g];
        g_ldp[(size_t)(row0 + tid) * NT2 + blockIdx.x] = s;
    }
}

// ---------------- prep + finalize -------------------------------------------
__global__ __launch_bounds__(256) void k_prep_a1(const float* __restrict__ v_in,
                                                 float* __restrict__ out)
{
    int i = blockIdx.x * 256 + threadIdx.x;          // float4 index over [BQ,128]
    if (i >= BQ * 128) return;
    int row = i >> 7, c4 = i & 127;
    float4 v = ((const float4*)v_in)[(size_t)row * 256 + c4];
    ((float4*)out)[(size_t)row * 256 + c4] = v;       // passive copy
    __half2 h0 = __floats2half2_rn(v.x - 0.5f, v.y - 0.5f);
    __half2 h1 = __floats2half2_rn(v.z - 0.5f, v.w - 0.5f);
    __half2* ph = (__half2*)&g_a1[(size_t)row * HDIM + c4 * 4];
    ph[0] = h0; ph[1] = h1;
}

__device__ __forceinline__ void prep_wt_body(
    const float* __restrict__ W, __half* th, int N)
{
    __shared__ float t[32][33];
    int n0 = blockIdx.x * 32, k0 = blockIdx.y * 32;
    int tx = threadIdx.x, ty = threadIdx.y;
#pragma unroll
    for (int i = 0; i < 4; ++i)
        t[ty + 8 * i][tx] = W[(size_t)(k0 + ty + 8 * i) * N + n0 + tx];
    __syncthreads();
#pragma unroll
    for (int i = 0; i < 4; ++i) {
        float v = t[tx][ty + 8 * i];
        th[(size_t)(n0 + ty + 8 * i) * HDIM + k0 + tx] = __float2half_rn(v);
    }
}
__global__ void k_prep_w1(const float* __restrict__ W){ prep_wt_body(W, g_w1, HDIM); }
__global__ void k_prep_w2(const float* __restrict__ W){ prep_wt_body(W, g_w2, HK);   }

__global__ __launch_bounds__(256) void k_finalize(const float* __restrict__ logd,
                                                  float* __restrict__ dout)
{
    int b = blockIdx.x * 256 + threadIdx.x;
    if (b < BQ) {
        float s = 0.f;
        const float4* p = (const float4*)&g_ldp[(size_t)b * NT2];
#pragma unroll
        for (int i = 0; i < NT2 / 4; ++i) {
            float4 v = p[i];
            s += v.x + v.y + v.z + v.w;
        }
        dout[(size_t)BQ * 1024 + b] = logd[b] - s;
    }
}

// ---------------- launch -----------------------------------------------------
extern "C" void kernel_launch(void* const* d_in, const int* in_sizes, int n_in,
                              void* d_out, int out_size)
{
    const float* v_in = (const float*)d_in[0];
    const float* logd = (const float*)d_in[1];
    const float* W1   = (const float*)d_in[2];
    const float* b1   = (const float*)d_in[3];
    const float* W2   = (const float*)d_in[4];
    const float* b2   = (const float*)d_in[5];
    float* out = (float*)d_out;

    cudaFuncSetAttribute(k_gemm1_tc, cudaFuncAttributeMaxDynamicSharedMemorySize, DYNSMEM);
    cudaFuncSetAttribute(k_gemm2_tc, cudaFuncAttributeMaxDynamicSharedMemorySize, DYNSMEM);

    k_prep_a1<<<(BQ * 128 + 255) / 256, 256>>>(v_in, out);
    k_prep_w1<<<dim3(16, 16),  dim3(32, 8)>>>(W1);
    k_prep_w2<<<dim3(256, 16), dim3(32, 8)>>>(W2);
    k_gemm1_tc<<<dim3(4, 64),  256, DYNSMEM>>>(b1);
    k_gemm2_tc<<<dim3(64, 64), 256, DYNSMEM>>>(v_in, b2, out);
    k_finalize<<<32, 256>>>(logd, out);
}

// round 9
// speedup vs baseline: 2.5390x; 1.0479x over previous
#include <cuda_runtime.h>
#include <cuda_fp16.h>
#include <cstdint>

#define BQ 8192
#define HDIM 512
#define HK 8192
#define NT2 64               // gemm2 n-tiles = 8192/128
#define NC 8                 // k chunks of 64
#define STAGE_BYTES 32768    // A 16K + B 16K
#define DYN1 98304           // gemm1: 3 stages
#define DYN2 106496          // gemm2: 3 stages + vbuf 4K + red 4K

// ---------------- device scratch (no cudaMalloc allowed) -------------------
__device__ __align__(16) __half g_a1[BQ*HDIM];
__device__ __align__(16) __half g_h [BQ*HDIM];
__device__ __align__(16) __half g_w1[HDIM*HDIM];
__device__ __align__(16) __half g_w2[(size_t)HK*HDIM];
__device__ float g_ldp[(size_t)BQ*NT2];

// ---------------- helpers ---------------------------------------------------
__device__ __forceinline__ uint32_t smem_u32(const void* p){
    uint32_t a;
    asm("{ .reg .u64 t; cvta.to.shared.u64 t, %1; cvt.u32.u64 %0, t; }" : "=r"(a) : "l"(p));
    return a;
}
__device__ __forceinline__ void cp16(uint32_t dst, const void* src){
    asm volatile("cp.async.cg.shared.global [%0], [%1], 16;" :: "r"(dst), "l"(src));
}
__device__ __forceinline__ void cp_commit(){
    asm volatile("cp.async.commit_group;" ::: "memory");
}
template<int N> __device__ __forceinline__ void cp_wait(){
    asm volatile("cp.async.wait_group %0;" :: "n"(N) : "memory");
}
__device__ __forceinline__ void ldsm4(uint32_t* r, uint32_t addr){
    asm volatile("ldmatrix.sync.aligned.m8n8.x4.shared.b16 {%0,%1,%2,%3}, [%4];"
        : "=r"(r[0]), "=r"(r[1]), "=r"(r[2]), "=r"(r[3]) : "r"(addr));
}
__device__ __forceinline__ void mma16816(float* d, const uint32_t* a, const uint32_t* b){
    asm volatile("mma.sync.aligned.m16n8k16.row.col.f32.f16.f16.f32 "
        "{%0,%1,%2,%3},{%4,%5,%6,%7},{%8,%9},{%0,%1,%2,%3};"
        : "+f"(d[0]), "+f"(d[1]), "+f"(d[2]), "+f"(d[3])
        : "r"(a[0]), "r"(a[1]), "r"(a[2]), "r"(a[3]), "r"(b[0]), "r"(b[1]));
}
__device__ __forceinline__ float fast_tanh(float x){
    x = fminf(fmaxf(x, -15.f), 15.f);
    float e = __expf(2.f * x);
    return __fdividef(e - 1.f, e + 1.f);
}

// ---------------- mainloop --------------------------------------------------
__device__ __forceinline__ void issue_chunk(
    int c, uint32_t sbase,
    const __half* __restrict__ a, const __half* __restrict__ b,
    int row0, int n0, int tid)
{
    const int kk = c << 6;
#pragma unroll
    for (int j = 0; j < 4; ++j) {                // A: 128 rows x 128B
        int i = tid + 256 * j;
        int r = i >> 3, q = i & 7;
        uint32_t sw = (uint32_t)(r * 128) + ((uint32_t)(q ^ (r & 7)) << 4);
        cp16(sbase + sw, a + (size_t)(row0 + r) * HDIM + kk + q * 8);
    }
#pragma unroll
    for (int j = 0; j < 4; ++j) {                // B: 128 n-rows x 128B
        int i = tid + 256 * j;
        int r = i >> 3, q = i & 7;
        uint32_t sw = (uint32_t)(r * 128) + ((uint32_t)(q ^ (r & 7)) << 4);
        cp16(sbase + 16384u + sw, b + (size_t)(n0 + r) * HDIM + kk + q * 8);
    }
    cp_commit();
}

__device__ __forceinline__ void gemm_mainloop(
    const __half* a, const __half* b, int row0, int n0,
    uint32_t sb, int tid, int lane, int wm, int wn,
    float acc[4][4][4])
{
#pragma unroll
    for (int mi = 0; mi < 4; ++mi)
#pragma unroll
        for (int ni = 0; ni < 4; ++ni)
#pragma unroll
            for (int q = 0; q < 4; ++q) acc[mi][ni][q] = 0.f;

    const int arow = wm * 64 + (lane & 15);
    const int ahl  = lane >> 4;
    const int brow = wn * 32 + (lane & 7) + ((lane >> 4) << 3);
    const int bhl  = (lane >> 3) & 1;

    issue_chunk(0, sb,               a, b, row0, n0, tid);
    issue_chunk(1, sb + STAGE_BYTES, a, b, row0, n0, tid);

    for (int i = 0; i < NC; ++i) {
        if (i < NC - 1) cp_wait<1>();
        else            cp_wait<0>();
        __syncthreads();                 // stage i ready; slot (i-1)%3 drained

        int j = i + 2;                   // prefetch into slot (i+2)%3
        if (j < NC) {
            uint32_t slot = (uint32_t)(j % 3) * STAGE_BYTES;
            issue_chunk(j, sb + slot, a, b, row0, n0, tid);
        }

        uint32_t st = sb + (uint32_t)(i % 3) * STAGE_BYTES;
        uint32_t bb = st + 16384u;
#pragma unroll
        for (int ks = 0; ks < 4; ++ks) {
            uint32_t bf[2][4];
#pragma unroll
            for (int bi = 0; bi < 2; ++bi) {
                int r = brow + bi * 16;
                uint32_t addr = bb + (uint32_t)(r * 128)
                              + ((uint32_t)((ks * 2 + bhl) ^ (r & 7)) << 4);
                ldsm4(bf[bi], addr);
            }
            uint32_t af[4][4];
#pragma unroll
            for (int mi = 0; mi < 4; ++mi) {
                int r = arow + mi * 16;
                uint32_t addr = st + (uint32_t)(r * 128)
                              + ((uint32_t)((ks * 2 + ahl) ^ (r & 7)) << 4);
                ldsm4(af[mi], addr);
            }
#pragma unroll
            for (int mi = 0; mi < 4; ++mi)
#pragma unroll
                for (int ni = 0; ni < 4; ++ni)
                    mma16816(acc[mi][ni], af[mi], &bf[ni >> 1][(ni & 1) * 2]);
        }
    }
}

// ---------------- GEMM1: h = tanh((v_p-0.5)@W1+b1) -> fp16 (reg epilogue) ---
__global__ __launch_bounds__(256, 2) void k_gemm1_tc(const float* __restrict__ b1)
{
    extern __shared__ char dsm[];
    const int tid  = threadIdx.x;
    const int wid  = tid >> 5;
    const int lane = tid & 31;
    const int wm   = wid & 1, wn = wid >> 1;
    const int l3   = lane & 3, gid = lane >> 2;
    const int row0 = blockIdx.y * 128;
    const int n0   = blockIdx.x * 128;

    float acc[4][4][4];
    gemm_mainloop(g_a1, g_w1, row0, n0, smem_u32(dsm), tid, lane, wm, wn, acc);

    float b1v[4][2];
#pragma unroll
    for (int ni = 0; ni < 4; ++ni) {
        int c = n0 + wn * 32 + ni * 8 + l3 * 2;
        b1v[ni][0] = b1[c]; b1v[ni][1] = b1[c + 1];
    }
#pragma unroll
    for (int mi = 0; mi < 4; ++mi) {
        int r = row0 + wm * 64 + mi * 16 + gid;
#pragma unroll
        for (int ni = 0; ni < 4; ++ni) {
            int cg = n0 + wn * 32 + ni * 8 + l3 * 2;
            float t0 = fast_tanh(acc[mi][ni][0] + b1v[ni][0]);
            float t1 = fast_tanh(acc[mi][ni][1] + b1v[ni][1]);
            float t2 = fast_tanh(acc[mi][ni][2] + b1v[ni][0]);
            float t3 = fast_tanh(acc[mi][ni][3] + b1v[ni][1]);
            *(__half2*)&g_h[(size_t)r * HDIM + cg]       = __floats2half2_rn(t0, t1);
            *(__half2*)&g_h[(size_t)(r + 8) * HDIM + cg] = __floats2half2_rn(t2, t3);
        }
    }
}

// ---------------- GEMM2 fused (register epilogue, quad-shuffle softmax) -----
__device__ __forceinline__ void epi_row(
    float a0, float a1, float a2, float a3, const float* bv,
    int j0, int j1, int j2, int j3,
    const float* __restrict__ v_in, int grow, int h, int l3,
    float* vbuf, float* redb, int r, int hl)
{
    float e0 = __expf(fast_tanh(a0 + bv[0]));
    float e1 = __expf(fast_tanh(a1 + bv[1]));
    float e2 = __expf(fast_tanh(a2 + bv[2]));
    float e3 = __expf(fast_tanh(a3 + bv[3]));
    float s = e0 + e1 + e2 + e3;
    float v = v_in[(size_t)grow * 1024 + 512 + h];
    int kk = (int)(v * 16.f); kk = kk < 0 ? 0 : (kk > 15 ? 15 : kk);
    float pref = (j0 < kk ? e0 : 0.f) + (j1 < kk ? e1 : 0.f)
               + (j2 < kk ? e2 : 0.f) + (j3 < kk ? e3 : 0.f);
    float pk = (j0 == kk) ? e0 : ((j1 == kk) ? e1 : ((j2 == kk) ? e2 : ((j3 == kk) ? e3 : 0.f)));
    s    += __shfl_xor_sync(0xffffffffu, s,    1);
    s    += __shfl_xor_sync(0xffffffffu, s,    2);
    pref += __shfl_xor_sync(0xffffffffu, pref, 1);
    pref += __shfl_xor_sync(0xffffffffu, pref, 2);
    pk   += __shfl_xor_sync(0xffffffffu, pk,   1);
    pk   += __shfl_xor_sync(0xffffffffu, pk,   2);
    if (l3 == 0) {
        float inv   = __fdividef(1.f, s);
        float p     = pk * inv;
        float y     = pref * inv;
        float alpha = v * 16.f - (float)kk;
        vbuf[r * 8 + hl] = y + alpha * p;
        redb[r * 8 + hl] = __logf(p);
    }
}

__global__ __launch_bounds__(256, 2) void k_gemm2_tc(
    const float* __restrict__ v_in, const float* __restrict__ b2,
    float* __restrict__ dout)
{
    extern __shared__ char dsm[];
    float* vbuf = (float*)(dsm + 3 * STAGE_BYTES);   // [128][8]
    float* redb = vbuf + 1024;                        // [128][8]
    const int tid  = threadIdx.x;
    const int wid  = tid >> 5;
    const int lane = tid & 31;
    const int wm   = wid & 1, wn = wid >> 1;
    const int l3   = lane & 3, gid = lane >> 2;
    const int row0 = blockIdx.y * 128;
    const int n0   = blockIdx.x * 128;
    const int hbase = n0 >> 4;

    float acc[4][4][4];
    gemm_mainloop(g_h, g_w2, row0, n0, smem_u32(dsm), tid, lane, wm, wn, acc);

    const int j0 = l3 * 2, j1 = j0 + 1, j2 = j0 + 8, j3 = j0 + 9;
    float b2v[2][4];
#pragma unroll
    for (int g = 0; g < 2; ++g) {
        int cb = n0 + wn * 32 + g * 16;
        b2v[g][0] = b2[cb + j0]; b2v[g][1] = b2[cb + j1];
        b2v[g][2] = b2[cb + j2]; b2v[g][3] = b2[cb + j3];
    }
#pragma unroll
    for (int mi = 0; mi < 4; ++mi) {
        int r = wm * 64 + mi * 16 + gid;
#pragma unroll
        for (int g = 0; g < 2; ++g) {
            int hl = wn * 2 + g;
            int h  = hbase + hl;
            epi_row(acc[mi][2*g][0], acc[mi][2*g][1], acc[mi][2*g+1][0], acc[mi][2*g+1][1],
                    b2v[g], j0, j1, j2, j3, v_in, row0 + r, h, l3, vbuf, redb, r, hl);
            epi_row(acc[mi][2*g][2], acc[mi][2*g][3], acc[mi][2*g+1][2], acc[mi][2*g+1][3],
                    b2v[g], j0, j1, j2, j3, v_in, row0 + r + 8, h, l3, vbuf, redb, r + 8, hl);
        }
    }
    __syncthreads();

    {   // coalesced v_out_active writes
        int r = tid >> 1, c0 = (tid & 1) * 4;
        float4 w = *(float4*)&vbuf[r * 8 + c0];
        *(float4*)&dout[(size_t)(row0 + r) * 1024 + 512 + hbase + c0] = w;
    }
    if (tid < 128) {
        float s = 0.f;
#pragma unroll
        for (int g = 0; g < 8; ++g) s += redb[tid * 8 + g];
        g_ldp[(size_t)(row0 + tid) * NT2 + blockIdx.x] = s;
    }
}

// ---------------- merged prep + finalize ------------------------------------
__device__ __forceinline__ void prep_wt(
    const float* __restrict__ W, __half* th, int N, int bx, int by, int tid)
{
    __shared__ float t[32][33];
    int n0 = bx * 32, k0 = by * 32;
    int tx = tid & 31, ty = tid >> 5;
#pragma unroll
    for (int i = 0; i < 4; ++i)
        t[ty + 8 * i][tx] = W[(size_t)(k0 + ty + 8 * i) * N + n0 + tx];
    __syncthreads();
#pragma unroll
    for (int i = 0; i < 4; ++i)
        th[(size_t)(n0 + ty + 8 * i) * HDIM + k0 + tx] = __float2half_rn(t[tx][ty + 8 * i]);
}

__global__ __launch_bounds__(256) void k_prep(
    const float* __restrict__ v_in, const float* __restrict__ W1,
    const float* __restrict__ W2, float* __restrict__ out)
{
    int b = blockIdx.x, tid = threadIdx.x;
    if (b < 4096) {                       // a1 + passive copy
        int i = b * 256 + tid;            // float4 over [BQ,128]
        int row = i >> 7, c4 = i & 127;
        float4 v = ((const float4*)v_in)[(size_t)row * 256 + c4];
        ((float4*)out)[(size_t)row * 256 + c4] = v;
        __half2 h0 = __floats2half2_rn(v.x - 0.5f, v.y - 0.5f);
        __half2 h1 = __floats2half2_rn(v.z - 0.5f, v.w - 0.5f);
        __half2* ph = (__half2*)&g_a1[(size_t)row * HDIM + c4 * 4];
        ph[0] = h0; ph[1] = h1;
    } else if (b < 4352) {
        int bb = b - 4096;                // W1: 16 x 16
        prep_wt(W1, g_w1, HDIM, bb & 15, bb >> 4, tid);
    } else {
        int bb = b - 4352;                // W2: 256 x 16
        prep_wt(W2, g_w2, HK, bb & 255, bb >> 8, tid);
    }
}

__global__ __launch_bounds__(256) void k_finalize(const float* __restrict__ logd,
                                                  float* __restrict__ dout)
{
    int b = blockIdx.x * 256 + threadIdx.x;
    if (b < BQ) {
        float s = 0.f;
        const float4* p = (const float4*)&g_ldp[(size_t)b * NT2];
#pragma unroll
        for (int i = 0; i < NT2 / 4; ++i) {
            float4 v = p[i];
            s += v.x + v.y + v.z + v.w;
        }
        dout[(size_t)BQ * 1024 + b] = logd[b] - s;
    }
}

// ---------------- launch -----------------------------------------------------
extern "C" void kernel_launch(void* const* d_in, const int* in_sizes, int n_in,
                              void* d_out, int out_size)
{
    const float* v_in = (const float*)d_in[0];
    const float* logd = (const float*)d_in[1];
    const float* W1   = (const float*)d_in[2];
    const float* b1   = (const float*)d_in[3];
    const float* W2   = (const float*)d_in[4];
    const float* b2   = (const float*)d_in[5];
    float* out = (float*)d_out;

    cudaFuncSetAttribute(k_gemm1_tc, cudaFuncAttributeMaxDynamicSharedMemorySize, DYN1);
    cudaFuncSetAttribute(k_gemm2_tc, cudaFuncAttributeMaxDynamicSharedMemorySize, DYN2);

    k_prep<<<8448, 256>>>(v_in, W1, W2, out);
    k_gemm1_tc<<<dim3(4, 64),  256, DYN1>>>(b1);
    k_gemm2_tc<<<dim3(64, 64), 256, DYN2>>>(v_in, b2, out);
    k_finalize<<<32, 256>>>(logd, out);
}